// round 14
// baseline (speedup 1.0000x reference)
#include <cuda_runtime.h>
#include <cuda_bf16.h>
#include <cuda_fp16.h>
#include <cuda_fp8.h>
#include <math.h>
#include <stdint.h>

// Problem constants
#define R      4096      // B*T
#define D      1024
#define DKD    256       // DK
#define NKEYS  32768
#define DM     256
#define KN     8         // K_NEIGHBORS
#define FF     (KN*DM)   // 2048
#define CAP    1024
#define MAXKEEP 64
#define CUT_LG  131.0f
#define DELTA_S 12.0f    // fp8 scan pre-filter threshold (6.55 exact + fp8 noise margin)

// tensor scan tiling: 9 uneven key-splits per 128-token block -> 288 CTAs
#define TOKS   128
#define KEYT   128
#define KSPLIT 9

// ---------------- scratch (static device globals; no allocation) ----------------
__device__ __align__(16) float g_q[R * DKD];
__device__ __align__(16) float g_q2[R];
__device__ __align__(16) float g_k2[NKEYS];
__device__ __align__(16) int   g_cidx[(size_t)R * CAP];
__device__ __align__(16) int   g_cnt[R];
__device__ __align__(16) unsigned char g_keys_f8[(size_t)NKEYS * DKD];
__device__ __align__(16) unsigned char g_q_f8[(size_t)R * DKD];
// fp16 operands for the W_out GEMM
__device__ __align__(16) __half g_a16[(size_t)R * FF];
__device__ __align__(16) __half g_w16[(size_t)D * FF];
// split-fp16 operands for the q projection GEMM
__device__ __align__(16) __half g_xh[(size_t)R * D];
__device__ __align__(16) __half g_xl[(size_t)R * D];
__device__ __align__(16) __half g_wih[(size_t)DKD * D];
__device__ __align__(16) __half g_wil[(size_t)DKD * D];

// ---------------- PTX helpers ----------------
__device__ __forceinline__ uint32_t smem_u32(const void* p) {
    uint32_t a;
    asm("{ .reg .u64 t; cvta.to.shared.u64 t, %1; cvt.u32.u64 %0, t; }" : "=r"(a) : "l"(p));
    return a;
}
#define CP_ASYNC16(dst, src) \
    asm volatile("cp.async.cg.shared.global [%0], [%1], 16;" \
                 :: "r"((uint32_t)(dst)), "l"(__cvta_generic_to_global(src)) : "memory")
#define CP_COMMIT()    asm volatile("cp.async.commit_group;" ::: "memory")
#define CP_WAIT(n)     asm volatile("cp.async.wait_group %0;" :: "n"(n) : "memory")

#define LDSM_X4(r0, r1, r2, r3, addr) \
    asm volatile("ldmatrix.sync.aligned.m8n8.x4.shared.b16 {%0,%1,%2,%3}, [%4];" \
                 : "=r"(r0), "=r"(r1), "=r"(r2), "=r"(r3) : "r"(addr))

#define MMA16816H(d, a, b) \
    asm volatile("mma.sync.aligned.m16n8k16.row.col.f32.f16.f16.f32 " \
                 "{%0,%1,%2,%3}, {%4,%5,%6,%7}, {%8,%9}, {%0,%1,%2,%3};" \
                 : "+f"((d)[0]), "+f"((d)[1]), "+f"((d)[2]), "+f"((d)[3]) \
                 : "r"((a)[0]), "r"((a)[1]), "r"((a)[2]), "r"((a)[3]), \
                   "r"((b)[0]), "r"((b)[1]))

#define MMA16832F8(d, a, b) \
    asm volatile("mma.sync.aligned.m16n8k32.row.col.f32.e4m3.e4m3.f32 " \
                 "{%0,%1,%2,%3}, {%4,%5,%6,%7}, {%8,%9}, {%0,%1,%2,%3};" \
                 : "+f"((d)[0]), "+f"((d)[1]), "+f"((d)[2]), "+f"((d)[3]) \
                 : "r"((a)[0]), "r"((a)[1]), "r"((a)[2]), "r"((a)[3]), \
                   "r"((b)[0]), "r"((b)[1]))

// ordered-float encoding for unsigned atomicMax
__device__ __forceinline__ unsigned fenc(float f) {
    unsigned u = __float_as_uint(f);
    return (u & 0x80000000u) ? ~u : (u | 0x80000000u);
}
__device__ __forceinline__ float fdec(unsigned e) {
    return __uint_as_float((e & 0x80000000u) ? (e & 0x7fffffffu) : ~e);
}

// ---------------- device helpers for prep ----------------
__device__ __forceinline__ void prep_fp8_row(const float* __restrict__ src,
                                             unsigned char* __restrict__ dst,
                                             float* __restrict__ sumsq,
                                             int* __restrict__ cnt,
                                             int row, int lane) {
    const float4* p = (const float4*)(src + (size_t)row * DKD);
    float4 v0 = p[lane * 2], v1 = p[lane * 2 + 1];
    float s = v0.x * v0.x;
    s = fmaf(v0.y, v0.y, s); s = fmaf(v0.z, v0.z, s); s = fmaf(v0.w, v0.w, s);
    s = fmaf(v1.x, v1.x, s); s = fmaf(v1.y, v1.y, s);
    s = fmaf(v1.z, v1.z, s); s = fmaf(v1.w, v1.w, s);
    #pragma unroll
    for (int o = 16; o; o >>= 1) s += __shfl_xor_sync(0xffffffffu, s, o);
    if (lane == 0) {
        sumsq[row] = s;
        if (cnt) cnt[row] = 0;
    }
    uint32_t p0 = __nv_cvt_float2_to_fp8x2(make_float2(v0.x, v0.y), __NV_SATFINITE, __NV_E4M3);
    uint32_t p1 = __nv_cvt_float2_to_fp8x2(make_float2(v0.z, v0.w), __NV_SATFINITE, __NV_E4M3);
    uint32_t p2 = __nv_cvt_float2_to_fp8x2(make_float2(v1.x, v1.y), __NV_SATFINITE, __NV_E4M3);
    uint32_t p3 = __nv_cvt_float2_to_fp8x2(make_float2(v1.z, v1.w), __NV_SATFINITE, __NV_E4M3);
    uint2 w;
    w.x = (p0 & 0xffffu) | (p1 << 16);
    w.y = (p2 & 0xffffu) | (p3 << 16);
    *(uint2*)(dst + (size_t)row * DKD + lane * 8) = w;
}

__device__ __forceinline__ void split16_elem(const float* __restrict__ src,
                                             __half* __restrict__ hi, __half* __restrict__ lo,
                                             int idx) {
    float4 v = ((const float4*)src)[idx];
    float h0 = __half2float(__float2half_rn(v.x));
    float h1 = __half2float(__float2half_rn(v.y));
    float h2 = __half2float(__float2half_rn(v.z));
    float h3 = __half2float(__float2half_rn(v.w));
    __half2* dh = (__half2*)hi;
    __half2* dl = (__half2*)lo;
    dh[idx * 2 + 0] = __floats2half2_rn(h0, h1);
    dh[idx * 2 + 1] = __floats2half2_rn(h2, h3);
    dl[idx * 2 + 0] = __floats2half2_rn(v.x - h0, v.y - h1);
    dl[idx * 2 + 1] = __floats2half2_rn(v.z - h2, v.w - h3);
}

// ---------------- merged prep: keys fp8+k2 | W_out->fp16 | x,W_in -> split fp16 ----
#define PREP_KB     (NKEYS / 8)             // 4096
#define PREP_WOUT   2048
#define PREP_X      4096
#define PREP_WIN    256
#define PREP_BLOCKS (PREP_KB + PREP_WOUT + PREP_X + PREP_WIN)

__global__ void prep_all_kernel(const float* __restrict__ keys, unsigned char* __restrict__ kf,
                                float* __restrict__ k2,
                                const float* __restrict__ W_out, __half* __restrict__ w16,
                                const float* __restrict__ x, __half* __restrict__ xh, __half* __restrict__ xl,
                                const float* __restrict__ W_in, __half* __restrict__ wih, __half* __restrict__ wil) {
    int b = blockIdx.x, tid = threadIdx.x;
    if (b < PREP_KB) {
        int row = b * 8 + (tid >> 5);
        prep_fp8_row(keys, kf, k2, nullptr, row, tid & 31);
    } else if (b < PREP_KB + PREP_WOUT) {
        int i = (b - PREP_KB) * 256 + tid;
        float4 v = ((const float4*)W_out)[i];
        __half2* d = (__half2*)w16;
        d[i * 2 + 0] = __floats2half2_rn(v.x, v.y);
        d[i * 2 + 1] = __floats2half2_rn(v.z, v.w);
    } else if (b < PREP_KB + PREP_WOUT + PREP_X) {
        int i = (b - PREP_KB - PREP_WOUT) * 256 + tid;
        split16_elem(x, xh, xl, i);
    } else {
        int i = (b - PREP_KB - PREP_WOUT - PREP_X) * 256 + tid;
        split16_elem(W_in, wih, wil, i);
    }
}

// ---------------- q prep: q2 + fp8 convert + cnt reset ----------------
__global__ void prep_q_kernel(const float* __restrict__ src, unsigned char* __restrict__ dst,
                              float* __restrict__ sumsq, int* __restrict__ cnt) {
    int row = blockIdx.x * 8 + (threadIdx.x >> 5);
    prep_fp8_row(src, dst, sumsq, cnt, row, threadIdx.x & 31);
}

// ---------------- q projection: split-fp16 tensor MMA, q = x @ W_in^T + b_in ----
#define QI_AH   0
#define QI_AL   8192
#define QI_BH   16384
#define QI_BL   24576
#define QI_BUF  32768
#define QI_BIAS 65536
#define SMEM_QIN 65792

__global__ void __launch_bounds__(256, 2) qin_mma_kernel(
    const __half* __restrict__ xh, const __half* __restrict__ xl,
    const __half* __restrict__ wh, const __half* __restrict__ wl,
    const float* __restrict__ bias, float* __restrict__ C)
{
    extern __shared__ char smem[];
    uint32_t sb = smem_u32(smem);
    float* biash = (float*)(smem + QI_BIAS);

    int tid  = threadIdx.x;
    int lane = tid & 31, wid = tid >> 5;
    int m0 = blockIdx.x * 64, n0 = blockIdx.y * 64;
    int mbase = (wid >> 1) * 16;
    int nbase = (wid & 1) * 32;

    if (tid < 64) biash[tid] = bias[n0 + tid];

    auto load_tile = [&](uint32_t dst, const __half* src, int row0, int k0) {
        const char* base = (const char*)(src + (size_t)row0 * D + k0);
        for (int i = tid; i < 512; i += 256) {
            int row = i >> 3, c16 = i & 7;
            int colb = c16 * 16;
            uint32_t sw = (uint32_t)(colb ^ ((row & 7) << 4));
            CP_ASYNC16(sb + dst + row * 128 + sw, base + (size_t)row * (D * 2) + colb);
        }
    };

    load_tile(QI_AH, xh, m0, 0);
    load_tile(QI_AL, xl, m0, 0);
    load_tile(QI_BH, wh, n0, 0);
    load_tile(QI_BL, wl, n0, 0);
    CP_COMMIT();

    float acc[4][4] = {};

    const int NCH = D / 64;   // 16
    for (int j = 0; j < NCH; j++) {
        uint32_t buf = (j & 1) ? QI_BUF : 0;
        if (j + 1 < NCH) {
            uint32_t nb = ((j + 1) & 1) ? QI_BUF : 0;
            int k0 = (j + 1) * 64;
            load_tile(nb + QI_AH, xh, m0, k0);
            load_tile(nb + QI_AL, xl, m0, k0);
            load_tile(nb + QI_BH, wh, n0, k0);
            load_tile(nb + QI_BL, wl, n0, k0);
            CP_COMMIT();
            CP_WAIT(1);
        } else {
            CP_WAIT(0);
        }
        __syncthreads();

        #pragma unroll
        for (int kk = 0; kk < 4; kk++) {
            uint32_t afh[4], afl[4];
            {
                int row = mbase + (lane & 15);
                int colb = kk * 32 + ((lane >> 4) << 4);
                uint32_t sw = (uint32_t)(colb ^ ((row & 7) << 4));
                LDSM_X4(afh[0], afh[1], afh[2], afh[3], sb + buf + QI_AH + row * 128 + sw);
                LDSM_X4(afl[0], afl[1], afl[2], afl[3], sb + buf + QI_AL + row * 128 + sw);
            }
            uint32_t bfh[4][2], bfl[4][2];
            #pragma unroll
            for (int bt = 0; bt < 2; bt++) {
                int nrow = nbase + bt * 16 + (lane & 7) + ((lane >> 4) << 3);
                int colb = kk * 32 + ((lane & 8) << 1);
                uint32_t sw = (uint32_t)(colb ^ ((nrow & 7) << 4));
                LDSM_X4(bfh[bt * 2][0], bfh[bt * 2][1], bfh[bt * 2 + 1][0], bfh[bt * 2 + 1][1],
                        sb + buf + QI_BH + nrow * 128 + sw);
                LDSM_X4(bfl[bt * 2][0], bfl[bt * 2][1], bfl[bt * 2 + 1][0], bfl[bt * 2 + 1][1],
                        sb + buf + QI_BL + nrow * 128 + sw);
            }
            #pragma unroll
            for (int nt = 0; nt < 4; nt++) {
                MMA16816H(acc[nt], afh, bfh[nt]);
                MMA16816H(acc[nt], afh, bfl[nt]);
                MMA16816H(acc[nt], afl, bfh[nt]);
            }
        }
        __syncthreads();
    }

    int r0 = m0 + mbase + (lane >> 2);
    #pragma unroll
    for (int nt = 0; nt < 4; nt++) {
        int cl = nbase + nt * 8 + 2 * (lane & 3);
        float b0 = biash[cl], b1 = biash[cl + 1];
        float2 v0 = make_float2(acc[nt][0] + b0, acc[nt][1] + b1);
        float2 v1 = make_float2(acc[nt][2] + b0, acc[nt][3] + b1);
        *(float2*)&C[(size_t)r0 * DKD + n0 + cl] = v0;
        *(float2*)&C[(size_t)(r0 + 8) * DKD + n0 + cl] = v1;
    }
}

// ---------------- fp8 tensor scan: barrier-free epilogue, warp-private maxima ----
#define SO_A    0
#define SO_B0   32768
#define SO_B1   65536
#define SO_K2   98304
#define SMEM_SCAN 98816

__global__ void __launch_bounds__(256, 2) scan_mma_kernel(
    const unsigned char* __restrict__ qf, const unsigned char* __restrict__ kf,
    const float* __restrict__ k2buf, int* __restrict__ cnt, int* __restrict__ cidx)
{
    extern __shared__ char smem[];
    uint32_t sb = smem_u32(smem);
    float* k2h = (float*)(smem + SO_K2);

    int tid  = threadIdx.x;
    int lane = tid & 31, wid = tid >> 5;
    int tok0 = blockIdx.x * TOKS;
    // uneven split: splits 0-3 get 29 tiles, splits 4-8 get 28 (4*29+5*28=256)
    int s = blockIdx.y;
    int tile0  = s * 28 + min(s, 4);
    int ntiles = (s < 4) ? 29 : 28;
    int keybase = tile0 * KEYT;
    int mbase = (wid >> 1) * 32;
    int nhalf = (wid & 1) * 64;

    {
        const char* abase = (const char*)(qf + (size_t)tok0 * DKD);
        const char* bbase = (const char*)(kf + (size_t)keybase * DKD);
        for (int i = tid; i < 2048; i += 256) {
            int row = i >> 4, c16 = i & 15;
            int colb = c16 * 16;
            uint32_t sw = (uint32_t)(colb ^ ((row & 7) << 4));
            CP_ASYNC16(sb + SO_A + row * 256 + sw, abase + row * 256 + colb);
            CP_ASYNC16(sb + SO_B0 + row * 256 + sw, bbase + row * 256 + colb);
        }
        CP_COMMIT();
    }

    float acc[2][8][4];
    // warp-private running max per (token-subrow, half); consistent across quads
    float runmax[2][2] = { { -1e30f, -1e30f }, { -1e30f, -1e30f } };

    for (int t = 0; t < ntiles; t++) {
        int key0 = keybase + t * KEYT;

        if (t + 1 < ntiles) {
            uint32_t nb = ((t + 1) & 1) ? SO_B1 : SO_B0;
            const char* bbase = (const char*)(kf + (size_t)(key0 + KEYT) * DKD);
            for (int i = tid; i < 2048; i += 256) {
                int row = i >> 4, c16 = i & 15;
                int colb = c16 * 16;
                uint32_t sw = (uint32_t)(colb ^ ((row & 7) << 4));
                CP_ASYNC16(sb + nb + row * 256 + sw, bbase + row * 256 + colb);
            }
            CP_COMMIT();
            CP_WAIT(1);
        } else {
            CP_WAIT(0);
        }
        __syncthreads();   // B-buffer reuse + k2h rewrite ordering

        if (tid < KEYT) k2h[tid] = 0.5f * k2buf[key0 + tid];
        __syncthreads();   // k2h visible before epilogue reads

        #pragma unroll
        for (int mt = 0; mt < 2; mt++)
            #pragma unroll
            for (int nt = 0; nt < 8; nt++)
                #pragma unroll
                for (int e = 0; e < 4; e++) acc[mt][nt][e] = 0.f;

        uint32_t bbuf = sb + ((t & 1) ? SO_B1 : SO_B0);
        #pragma unroll
        for (int kk = 0; kk < 8; kk++) {
            uint32_t a[2][4];
            #pragma unroll
            for (int mt = 0; mt < 2; mt++) {
                int row = mbase + mt * 16 + (lane & 15);
                int colb = kk * 32 + ((lane >> 4) << 4);
                uint32_t ad = sb + SO_A + row * 256 + (uint32_t)(colb ^ ((row & 7) << 4));
                LDSM_X4(a[mt][0], a[mt][1], a[mt][2], a[mt][3], ad);
            }
            uint32_t b[8][2];
            #pragma unroll
            for (int bt = 0; bt < 4; bt++) {
                int n = nhalf + bt * 16 + (lane & 7) + ((lane >> 4) << 3);
                int colb = kk * 32 + ((lane & 8) << 1);
                uint32_t bd = bbuf + n * 256 + (uint32_t)(colb ^ ((n & 7) << 4));
                LDSM_X4(b[bt * 2][0], b[bt * 2][1], b[bt * 2 + 1][0], b[bt * 2 + 1][1], bd);
            }
            #pragma unroll
            for (int mt = 0; mt < 2; mt++)
                #pragma unroll
                for (int nt = 0; nt < 8; nt++)
                    MMA16832F8(acc[mt][nt], a[mt], b[nt]);
        }

        // barrier-free epilogue: scores, quad max, warp-private threshold, select
        {
            float rm[2][2];
            #pragma unroll
            for (int mt = 0; mt < 2; mt++) { rm[mt][0] = -1e30f; rm[mt][1] = -1e30f; }
            #pragma unroll
            for (int mt = 0; mt < 2; mt++) {
                #pragma unroll
                for (int nt = 0; nt < 8; nt++) {
                    float kc0 = k2h[nhalf + nt * 8 + 2 * (lane & 3)];
                    float kc1 = k2h[nhalf + nt * 8 + 2 * (lane & 3) + 1];
                    acc[mt][nt][0] -= kc0; acc[mt][nt][1] -= kc1;
                    acc[mt][nt][2] -= kc0; acc[mt][nt][3] -= kc1;
                    rm[mt][0] = fmaxf(rm[mt][0], fmaxf(acc[mt][nt][0], acc[mt][nt][1]));
                    rm[mt][1] = fmaxf(rm[mt][1], fmaxf(acc[mt][nt][2], acc[mt][nt][3]));
                }
            }
            #pragma unroll
            for (int mt = 0; mt < 2; mt++) {
                #pragma unroll
                for (int e = 0; e < 2; e++) {
                    float v = rm[mt][e];
                    v = fmaxf(v, __shfl_xor_sync(0xffffffffu, v, 1));
                    v = fmaxf(v, __shfl_xor_sync(0xffffffffu, v, 2));
                    runmax[mt][e] = fmaxf(runmax[mt][e], v);
                }
            }
            #pragma unroll
            for (int mt = 0; mt < 2; mt++) {
                float th0 = runmax[mt][0] - DELTA_S;
                float th1 = runmax[mt][1] - DELTA_S;
                int r0 = mbase + mt * 16 + (lane >> 2);
                int tokA = tok0 + r0, tokB = tokA + 8;
                #pragma unroll
                for (int nt = 0; nt < 8; nt++) {
                    int keyc = key0 + nhalf + nt * 8 + 2 * (lane & 3);
                    if (acc[mt][nt][0] > th0) {
                        int pos = atomicAdd(&cnt[tokA], 1);
                        if (pos < CAP) cidx[(size_t)tokA * CAP + pos] = keyc;
                    }
                    if (acc[mt][nt][1] > th0) {
                        int pos = atomicAdd(&cnt[tokA], 1);
                        if (pos < CAP) cidx[(size_t)tokA * CAP + pos] = keyc + 1;
                    }
                    if (acc[mt][nt][2] > th1) {
                        int pos = atomicAdd(&cnt[tokB], 1);
                        if (pos < CAP) cidx[(size_t)tokB * CAP + pos] = keyc;
                    }
                    if (acc[mt][nt][3] > th1) {
                        int pos = atomicAdd(&cnt[tokB], 1);
                        if (pos < CAP) cidx[(size_t)tokB * CAP + pos] = keyc + 1;
                    }
                }
            }
        }
    }
}

// ---------------- exact rescore + 8-round recursion + gather (emits fp16) ----------
__global__ void recurse_kernel(const float* __restrict__ keys, const float* __restrict__ vals,
                               const float* __restrict__ qbuf, const float* __restrict__ q2buf,
                               const float* __restrict__ k2buf, const int* __restrict__ cnt,
                               const int* __restrict__ cidx,
                               __half* __restrict__ a16) {
    __shared__ float    qrow[DKD];
    __shared__ int      cidx_sh[CAP];
    __shared__ float    lg_all[CAP];
    __shared__ int      keep_idx[MAXKEEP];
    __shared__ float    keep_lg[MAXKEEP];
    __shared__ float    wmat[KN][MAXKEEP];
    __shared__ unsigned s_maxenc;
    __shared__ int      s_nkeep;

    int tok = blockIdx.x, tid = threadIdx.x;
    int lane = tid & 31, wid = tid >> 5;
    int n = min(cnt[tok], CAP);

    qrow[tid] = qbuf[(size_t)tok * DKD + tid];
    if (tid == 0) { s_maxenc = fenc(-1e30f); s_nkeep = 0; }
    for (int c = tid; c < n; c += 256) cidx_sh[c] = cidx[(size_t)tok * CAP + c];
    __syncthreads();

    float q2 = q2buf[tok];
    float4 q0 = *(const float4*)&qrow[lane * 4];
    float4 q1 = *(const float4*)&qrow[128 + lane * 4];
    for (int c0 = wid * 2; c0 < n; c0 += 16) {
        int kiA = cidx_sh[c0];
        bool hasB = (c0 + 1 < n);
        int kiB = hasB ? cidx_sh[c0 + 1] : kiA;
        const float4* kpA = (const float4*)(keys + (size_t)kiA * DKD);
        const float4* kpB = (const float4*)(keys + (size_t)kiB * DKD);
        float4 a0 = kpA[lane], a1 = kpA[lane + 32];
        float4 b0 = kpB[lane], b1 = kpB[lane + 32];
        float pA = q0.x * a0.x;
        pA = fmaf(q0.y, a0.y, pA); pA = fmaf(q0.z, a0.z, pA); pA = fmaf(q0.w, a0.w, pA);
        pA = fmaf(q1.x, a1.x, pA); pA = fmaf(q1.y, a1.y, pA);
        pA = fmaf(q1.z, a1.z, pA); pA = fmaf(q1.w, a1.w, pA);
        float pB = q0.x * b0.x;
        pB = fmaf(q0.y, b0.y, pB); pB = fmaf(q0.z, b0.z, pB); pB = fmaf(q0.w, b0.w, pB);
        pB = fmaf(q1.x, b1.x, pB); pB = fmaf(q1.y, b1.y, pB);
        pB = fmaf(q1.z, b1.z, pB); pB = fmaf(q1.w, b1.w, pB);
        #pragma unroll
        for (int o = 16; o; o >>= 1) {
            pA += __shfl_xor_sync(0xffffffffu, pA, o);
            pB += __shfl_xor_sync(0xffffffffu, pB, o);
        }
        if (lane == 0) {
            float lgA = -(q2 - 2.0f * pA + k2buf[kiA]) / 0.1f;
            lg_all[c0] = lgA;
            unsigned m = fenc(lgA);
            if (hasB) {
                float lgB = -(q2 - 2.0f * pB + k2buf[kiB]) / 0.1f;
                lg_all[c0 + 1] = lgB;
                unsigned mB = fenc(lgB);
                if (mB > m) m = mB;
            }
            atomicMax(&s_maxenc, m);
        }
    }
    __syncthreads();
    float cut = fdec(s_maxenc) - CUT_LG;
    for (int c = tid; c < n; c += 256) {
        if (lg_all[c] >= cut) {
            int pos = atomicAdd(&s_nkeep, 1);
            if (pos < MAXKEEP) {
                keep_idx[pos] = cidx_sh[c];
                keep_lg[pos]  = lg_all[c];
            }
        }
    }
    __syncthreads();
    int nk = min(s_nkeep, MAXKEEP);
    {
        int my = 0, rank = -1; float mylg = 0.f;
        if (tid < nk) {
            my = keep_idx[tid]; mylg = keep_lg[tid];
            rank = 0;
            for (int c = 0; c < nk; c++) rank += (keep_idx[c] < my);
        }
        __syncthreads();
        if (tid < nk) { keep_idx[rank] = my; keep_lg[rank] = mylg; }
        __syncthreads();
    }
    if (wid == 0) {
        for (int k = 0; k < KN; k++) {
            float lm = -1e30f;
            for (int c = lane; c < nk; c += 32) lm = fmaxf(lm, keep_lg[c]);
            #pragma unroll
            for (int o = 16; o; o >>= 1) lm = fmaxf(lm, __shfl_xor_sync(0xffffffffu, lm, o));
            float zs = 0.f;
            for (int c = lane; c < nk; c += 32) {
                float p = expf(keep_lg[c] - lm);
                wmat[k][c] = p;
                zs += p;
            }
            #pragma unroll
            for (int o = 16; o; o >>= 1) zs += __shfl_xor_sync(0xffffffffu, zs, o);
            float inv = 1.0f / zs;
            for (int c = lane; c < nk; c += 32) {
                float w = wmat[k][c] * inv;
                wmat[k][c] = w;
                keep_lg[c] += log1pf(-w + 1e-6f);
            }
            __syncwarp();
        }
    }
    __syncthreads();
    float a[KN] = {};
    for (int c = 0; c < nk; c++) {
        float v = vals[(size_t)keep_idx[c] * DM + tid];
        #pragma unroll
        for (int k = 0; k < KN; k++) a[k] = fmaf(wmat[k][c], v, a[k]);
    }
    #pragma unroll
    for (int k = 0; k < KN; k++)
        a16[(size_t)tok * FF + k * DM + tid] = __float2half_rn(a[k]);
}

// ---------------- W_out GEMM: fp16 tensor cores, double buffer, 2 CTA/SM ----------
#define WO_A    0
#define WO_B    16384
#define WO_BUF  32768
#define WO_BIAS 65536
#define SMEM_WOUT 66048

__global__ void __launch_bounds__(256, 2) wout_mma_kernel(
    const __half* __restrict__ a16, const __half* __restrict__ w16,
    const float* __restrict__ bias, float* __restrict__ C)
{
    extern __shared__ char smem[];
    uint32_t sb = smem_u32(smem);
    float* biash = (float*)(smem + WO_BIAS);

    int tid  = threadIdx.x;
    int lane = tid & 31, wid = tid >> 5;
    int m0 = blockIdx.x * 128, n0 = blockIdx.y * 128;
    int mbase = (wid >> 1) * 32;
    int nhalf = (wid & 1) * 64;

    if (tid < 128) biash[tid] = bias[n0 + tid];

    auto load_tile = [&](uint32_t dst, const __half* src, int row0, int k0) {
        const char* base = (const char*)(src + (size_t)row0 * FF + k0);
        for (int i = tid; i < 1024; i += 256) {
            int row = i >> 3, c16 = i & 7;
            int colb = c16 * 16;
            uint32_t sw = (uint32_t)(colb ^ ((row & 7) << 4));
            CP_ASYNC16(sb + dst + row * 128 + sw, base + (size_t)row * (FF * 2) + colb);
        }
    };

    load_tile(WO_A, a16, m0, 0);
    load_tile(WO_B, w16, n0, 0);
    CP_COMMIT();

    float acc[2][8][4] = {};

    const int NCH = FF / 64;   // 32
    for (int j = 0; j < NCH; j++) {
        uint32_t buf = (j & 1) ? WO_BUF : 0;
        if (j + 1 < NCH) {
            uint32_t nb = ((j + 1) & 1) ? WO_BUF : 0;
            int k0 = (j + 1) * 64;
            load_tile(nb + WO_A, a16, m0, k0);
            load_tile(nb + WO_B, w16, n0, k0);
            CP_COMMIT();
            CP_WAIT(1);
        } else {
            CP_WAIT(0);
        }
        __syncthreads();

        #pragma unroll
        for (int kk = 0; kk < 4; kk++) {
            uint32_t af[2][4];
            #pragma unroll
            for (int mt = 0; mt < 2; mt++) {
                int row = mbase + mt * 16 + (lane & 15);
                int colb = kk * 32 + ((lane >> 4) << 4);
                uint32_t sw = (uint32_t)(colb ^ ((row & 7) << 4));
                LDSM_X4(af[mt][0], af[mt][1], af[mt][2], af[mt][3],
                        sb + buf + WO_A + row * 128 + sw);
            }
            uint32_t bf[8][2];
            #pragma unroll
            for (int bt = 0; bt < 4; bt++) {
                int nrow = nhalf + bt * 16 + (lane & 7) + ((lane >> 4) << 3);
                int colb = kk * 32 + ((lane & 8) << 1);
                uint32_t sw = (uint32_t)(colb ^ ((nrow & 7) << 4));
                LDSM_X4(bf[bt * 2][0], bf[bt * 2][1], bf[bt * 2 + 1][0], bf[bt * 2 + 1][1],
                        sb + buf + WO_B + nrow * 128 + sw);
            }
            #pragma unroll
            for (int mt = 0; mt < 2; mt++)
                #pragma unroll
                for (int nt = 0; nt < 8; nt++)
                    MMA16816H(acc[mt][nt], af[mt], bf[nt]);
        }
        __syncthreads();
    }

    #pragma unroll
    for (int mt = 0; mt < 2; mt++) {
        int r0 = m0 + mbase + mt * 16 + (lane >> 2);
        #pragma unroll
        for (int nt = 0; nt < 8; nt++) {
            int cl = nhalf + nt * 8 + 2 * (lane & 3);
            float b0 = biash[cl], b1 = biash[cl + 1];
            float2 v0 = make_float2(acc[mt][nt][0] + b0, acc[mt][nt][1] + b1);
            float2 v1 = make_float2(acc[mt][nt][2] + b0, acc[mt][nt][3] + b1);
            *(float2*)&C[(size_t)r0 * D + n0 + cl] = v0;
            *(float2*)&C[(size_t)(r0 + 8) * D + n0 + cl] = v1;
        }
    }
}

// ---------------- RMSNorm (in place on d_out) ----------------
__global__ void rmsnorm_kernel(float* __restrict__ out, const float* __restrict__ rms_w) {
    __shared__ float wsum[8];
    __shared__ float s_tot;
    int tok = blockIdx.x, tid = threadIdx.x;
    float* row = out + (size_t)tok * D;
    float v[4];
    float ss = 0.f;
    #pragma unroll
    for (int e = 0; e < 4; e++) { v[e] = row[tid + e * 256]; ss = fmaf(v[e], v[e], ss); }
    #pragma unroll
    for (int o = 16; o; o >>= 1) ss += __shfl_xor_sync(0xffffffffu, ss, o);
    if ((tid & 31) == 0) wsum[tid >> 5] = ss;
    __syncthreads();
    if (tid == 0) {
        float t = 0.f;
        #pragma unroll
        for (int w = 0; w < 8; w++) t += wsum[w];
        s_tot = t;
    }
    __syncthreads();
    float var = s_tot / (float)D;
    float rs = 1.0f / sqrtf(var + 1e-6f);
    #pragma unroll
    for (int e = 0; e < 4; e++) {
        int d = tid + e * 256;
        row[d] = rms_w[d] * (v[e] * rs);
    }
}

// ---------------- host launch ----------------
extern "C" void kernel_launch(void* const* d_in, const int* in_sizes, int n_in,
                              void* d_out, int out_size) {
    const float* x     = (const float*)d_in[0];
    const float* keys  = (const float*)d_in[1];
    const float* vals  = (const float*)d_in[2];
    const float* W_in  = (const float*)d_in[3];
    const float* b_in  = (const float*)d_in[4];
    const float* W_out = (const float*)d_in[5];
    const float* b_out = (const float*)d_in[6];
    const float* rms_w = (const float*)d_in[7];
    float* out = (float*)d_out;
    (void)in_sizes; (void)n_in; (void)out_size;

    float *qp, *q2p, *k2p;
    int *cntp, *cidxp;
    unsigned char *kfp, *qfp;
    __half *a16p, *w16p, *xhp, *xlp, *wihp, *wilp;
    cudaGetSymbolAddress((void**)&qp,    g_q);
    cudaGetSymbolAddress((void**)&q2p,   g_q2);
    cudaGetSymbolAddress((void**)&k2p,   g_k2);
    cudaGetSymbolAddress((void**)&cntp,  g_cnt);
    cudaGetSymbolAddress((void**)&cidxp, g_cidx);
    cudaGetSymbolAddress((void**)&kfp,   g_keys_f8);
    cudaGetSymbolAddress((void**)&qfp,   g_q_f8);
    cudaGetSymbolAddress((void**)&a16p,  g_a16);
    cudaGetSymbolAddress((void**)&w16p,  g_w16);
    cudaGetSymbolAddress((void**)&xhp,   g_xh);
    cudaGetSymbolAddress((void**)&xlp,   g_xl);
    cudaGetSymbolAddress((void**)&wihp,  g_wih);
    cudaGetSymbolAddress((void**)&wilp,  g_wil);

    static int smem_set = 0;
    if (!smem_set) {
        cudaFuncSetAttribute(scan_mma_kernel, cudaFuncAttributeMaxDynamicSharedMemorySize, SMEM_SCAN);
        cudaFuncSetAttribute(wout_mma_kernel, cudaFuncAttributeMaxDynamicSharedMemorySize, SMEM_WOUT);
        cudaFuncSetAttribute(qin_mma_kernel,  cudaFuncAttributeMaxDynamicSharedMemorySize, SMEM_QIN);
        smem_set = 1;
    }

    // 1. merged prep: keys k2+fp8 | W_out fp16 | x, W_in split-fp16 (one launch)
    prep_all_kernel<<<PREP_BLOCKS, 256>>>(keys, kfp, k2p, W_out, w16p,
                                          x, xhp, xlp, W_in, wihp, wilp);
    // 2. q = x @ W_in^T + b_in (split-fp16 tensor cores, fp32-exact)
    qin_mma_kernel<<<dim3(R / 64, DKD / 64), 256, SMEM_QIN>>>(xhp, xlp, wihp, wilp, b_in, qp);
    // 3. q: q2 + fp8 convert + cnt reset (fused)
    prep_q_kernel<<<R / 8, 256>>>(qp, qfp, q2p, cntp);
    // 4. fp8 tensor-core qk scan + candidate selection (barrier-free epilogue)
    scan_mma_kernel<<<dim3(R / TOKS, KSPLIT), 256, SMEM_SCAN>>>(qfp, kfp, k2p, cntp, cidxp);
    // 5. exact rescore + 8-round recursion + gather -> fp16 nearest
    recurse_kernel<<<R, 256>>>(keys, vals, qp, q2p, k2p, cntp, cidxp, a16p);
    // 6. out = nearest @ W_out^T + b_out (fp16 tensor cores)
    wout_mma_kernel<<<dim3(R / 128, D / 128), 256, SMEM_WOUT>>>(a16p, w16p, b_out, out);
    // 7. RMSNorm * rms_w, in place
    rmsnorm_kernel<<<R, 256>>>(out, rms_w);
}

// round 15
// speedup vs baseline: 1.2500x; 1.2500x over previous
#include <cuda_runtime.h>
#include <cuda_bf16.h>
#include <cuda_fp16.h>
#include <cuda_fp8.h>
#include <math.h>
#include <stdint.h>

// Problem constants
#define R      4096      // B*T
#define D      1024
#define DKD    256       // DK
#define NKEYS  32768
#define DM     256
#define KN     8         // K_NEIGHBORS
#define FF     (KN*DM)   // 2048
#define CAP    1024
#define MAXKEEP 64
#define CUT_LG  131.0f
#define DELTA_S 11.5f    // fp8 scan pre-filter threshold (6.55 exact + ~8.5-sigma fp8 margin)

// tensor scan tiling: 9 uneven key-splits per 128-token block -> 288 CTAs
#define TOKS   128
#define KEYT   128
#define KSPLIT 9

// ---------------- scratch (static device globals; no allocation) ----------------
__device__ __align__(16) float g_q[R * DKD];
__device__ __align__(16) float g_q2[R];
__device__ __align__(16) float g_k2[NKEYS];
__device__ __align__(16) int   g_cidx[(size_t)R * CAP];
__device__ __align__(16) int   g_cnt[R];
__device__ __align__(16) unsigned char g_keys_f8[(size_t)NKEYS * DKD];
__device__ __align__(16) unsigned char g_q_f8[(size_t)R * DKD];
// fp16 operands for the W_out GEMM
__device__ __align__(16) __half g_a16[(size_t)R * FF];
__device__ __align__(16) __half g_w16[(size_t)D * FF];
// split-fp16 operands for the q projection GEMM
__device__ __align__(16) __half g_xh[(size_t)R * D];
__device__ __align__(16) __half g_xl[(size_t)R * D];
__device__ __align__(16) __half g_wih[(size_t)DKD * D];
__device__ __align__(16) __half g_wil[(size_t)DKD * D];

// ---------------- PTX helpers ----------------
__device__ __forceinline__ uint32_t smem_u32(const void* p) {
    uint32_t a;
    asm("{ .reg .u64 t; cvta.to.shared.u64 t, %1; cvt.u32.u64 %0, t; }" : "=r"(a) : "l"(p));
    return a;
}
#define CP_ASYNC16(dst, src) \
    asm volatile("cp.async.cg.shared.global [%0], [%1], 16;" \
                 :: "r"((uint32_t)(dst)), "l"(__cvta_generic_to_global(src)) : "memory")
#define CP_COMMIT()    asm volatile("cp.async.commit_group;" ::: "memory")
#define CP_WAIT(n)     asm volatile("cp.async.wait_group %0;" :: "n"(n) : "memory")

#define LDSM_X4(r0, r1, r2, r3, addr) \
    asm volatile("ldmatrix.sync.aligned.m8n8.x4.shared.b16 {%0,%1,%2,%3}, [%4];" \
                 : "=r"(r0), "=r"(r1), "=r"(r2), "=r"(r3) : "r"(addr))

#define MMA16816H(d, a, b) \
    asm volatile("mma.sync.aligned.m16n8k16.row.col.f32.f16.f16.f32 " \
                 "{%0,%1,%2,%3}, {%4,%5,%6,%7}, {%8,%9}, {%0,%1,%2,%3};" \
                 : "+f"((d)[0]), "+f"((d)[1]), "+f"((d)[2]), "+f"((d)[3]) \
                 : "r"((a)[0]), "r"((a)[1]), "r"((a)[2]), "r"((a)[3]), \
                   "r"((b)[0]), "r"((b)[1]))

#define MMA16832F8(d, a, b) \
    asm volatile("mma.sync.aligned.m16n8k32.row.col.f32.e4m3.e4m3.f32 " \
                 "{%0,%1,%2,%3}, {%4,%5,%6,%7}, {%8,%9}, {%0,%1,%2,%3};" \
                 : "+f"((d)[0]), "+f"((d)[1]), "+f"((d)[2]), "+f"((d)[3]) \
                 : "r"((a)[0]), "r"((a)[1]), "r"((a)[2]), "r"((a)[3]), \
                   "r"((b)[0]), "r"((b)[1]))

// ordered-float encoding for unsigned atomicMax
__device__ __forceinline__ unsigned fenc(float f) {
    unsigned u = __float_as_uint(f);
    return (u & 0x80000000u) ? ~u : (u | 0x80000000u);
}
__device__ __forceinline__ float fdec(unsigned e) {
    return __uint_as_float((e & 0x80000000u) ? (e & 0x7fffffffu) : ~e);
}

// ---------------- device helpers for prep ----------------
__device__ __forceinline__ void prep_fp8_row(const float* __restrict__ src,
                                             unsigned char* __restrict__ dst,
                                             float* __restrict__ sumsq,
                                             int* __restrict__ cnt,
                                             int row, int lane) {
    const float4* p = (const float4*)(src + (size_t)row * DKD);
    float4 v0 = p[lane * 2], v1 = p[lane * 2 + 1];
    float s = v0.x * v0.x;
    s = fmaf(v0.y, v0.y, s); s = fmaf(v0.z, v0.z, s); s = fmaf(v0.w, v0.w, s);
    s = fmaf(v1.x, v1.x, s); s = fmaf(v1.y, v1.y, s);
    s = fmaf(v1.z, v1.z, s); s = fmaf(v1.w, v1.w, s);
    #pragma unroll
    for (int o = 16; o; o >>= 1) s += __shfl_xor_sync(0xffffffffu, s, o);
    if (lane == 0) {
        sumsq[row] = s;
        if (cnt) cnt[row] = 0;
    }
    uint32_t p0 = __nv_cvt_float2_to_fp8x2(make_float2(v0.x, v0.y), __NV_SATFINITE, __NV_E4M3);
    uint32_t p1 = __nv_cvt_float2_to_fp8x2(make_float2(v0.z, v0.w), __NV_SATFINITE, __NV_E4M3);
    uint32_t p2 = __nv_cvt_float2_to_fp8x2(make_float2(v1.x, v1.y), __NV_SATFINITE, __NV_E4M3);
    uint32_t p3 = __nv_cvt_float2_to_fp8x2(make_float2(v1.z, v1.w), __NV_SATFINITE, __NV_E4M3);
    uint2 w;
    w.x = (p0 & 0xffffu) | (p1 << 16);
    w.y = (p2 & 0xffffu) | (p3 << 16);
    *(uint2*)(dst + (size_t)row * DKD + lane * 8) = w;
}

__device__ __forceinline__ void split16_elem(const float* __restrict__ src,
                                             __half* __restrict__ hi, __half* __restrict__ lo,
                                             int idx) {
    float4 v = ((const float4*)src)[idx];
    float h0 = __half2float(__float2half_rn(v.x));
    float h1 = __half2float(__float2half_rn(v.y));
    float h2 = __half2float(__float2half_rn(v.z));
    float h3 = __half2float(__float2half_rn(v.w));
    __half2* dh = (__half2*)hi;
    __half2* dl = (__half2*)lo;
    dh[idx * 2 + 0] = __floats2half2_rn(h0, h1);
    dh[idx * 2 + 1] = __floats2half2_rn(h2, h3);
    dl[idx * 2 + 0] = __floats2half2_rn(v.x - h0, v.y - h1);
    dl[idx * 2 + 1] = __floats2half2_rn(v.z - h2, v.w - h3);
}

// ---------------- merged prep: keys fp8+k2 | W_out->fp16 | x,W_in -> split fp16 ----
#define PREP_KB     (NKEYS / 8)             // 4096
#define PREP_WOUT   2048
#define PREP_X      4096
#define PREP_WIN    256
#define PREP_BLOCKS (PREP_KB + PREP_WOUT + PREP_X + PREP_WIN)

__global__ void prep_all_kernel(const float* __restrict__ keys, unsigned char* __restrict__ kf,
                                float* __restrict__ k2,
                                const float* __restrict__ W_out, __half* __restrict__ w16,
                                const float* __restrict__ x, __half* __restrict__ xh, __half* __restrict__ xl,
                                const float* __restrict__ W_in, __half* __restrict__ wih, __half* __restrict__ wil) {
    int b = blockIdx.x, tid = threadIdx.x;
    if (b < PREP_KB) {
        int row = b * 8 + (tid >> 5);
        prep_fp8_row(keys, kf, k2, nullptr, row, tid & 31);
    } else if (b < PREP_KB + PREP_WOUT) {
        int i = (b - PREP_KB) * 256 + tid;
        float4 v = ((const float4*)W_out)[i];
        __half2* d = (__half2*)w16;
        d[i * 2 + 0] = __floats2half2_rn(v.x, v.y);
        d[i * 2 + 1] = __floats2half2_rn(v.z, v.w);
    } else if (b < PREP_KB + PREP_WOUT + PREP_X) {
        int i = (b - PREP_KB - PREP_WOUT) * 256 + tid;
        split16_elem(x, xh, xl, i);
    } else {
        int i = (b - PREP_KB - PREP_WOUT - PREP_X) * 256 + tid;
        split16_elem(W_in, wih, wil, i);
    }
}

// ---------------- q prep: q2 + fp8 convert + cnt reset ----------------
__global__ void prep_q_kernel(const float* __restrict__ src, unsigned char* __restrict__ dst,
                              float* __restrict__ sumsq, int* __restrict__ cnt) {
    int row = blockIdx.x * 8 + (threadIdx.x >> 5);
    prep_fp8_row(src, dst, sumsq, cnt, row, threadIdx.x & 31);
}

// ---------------- q projection: split-fp16 tensor MMA, q = x @ W_in^T + b_in ----
#define QI_AH   0
#define QI_AL   8192
#define QI_BH   16384
#define QI_BL   24576
#define QI_BUF  32768
#define QI_BIAS 65536
#define SMEM_QIN 65792

__global__ void __launch_bounds__(256, 2) qin_mma_kernel(
    const __half* __restrict__ xh, const __half* __restrict__ xl,
    const __half* __restrict__ wh, const __half* __restrict__ wl,
    const float* __restrict__ bias, float* __restrict__ C)
{
    extern __shared__ char smem[];
    uint32_t sb = smem_u32(smem);
    float* biash = (float*)(smem + QI_BIAS);

    int tid  = threadIdx.x;
    int lane = tid & 31, wid = tid >> 5;
    int m0 = blockIdx.x * 64, n0 = blockIdx.y * 64;
    int mbase = (wid >> 1) * 16;
    int nbase = (wid & 1) * 32;

    if (tid < 64) biash[tid] = bias[n0 + tid];

    auto load_tile = [&](uint32_t dst, const __half* src, int row0, int k0) {
        const char* base = (const char*)(src + (size_t)row0 * D + k0);
        for (int i = tid; i < 512; i += 256) {
            int row = i >> 3, c16 = i & 7;
            int colb = c16 * 16;
            uint32_t sw = (uint32_t)(colb ^ ((row & 7) << 4));
            CP_ASYNC16(sb + dst + row * 128 + sw, base + (size_t)row * (D * 2) + colb);
        }
    };

    load_tile(QI_AH, xh, m0, 0);
    load_tile(QI_AL, xl, m0, 0);
    load_tile(QI_BH, wh, n0, 0);
    load_tile(QI_BL, wl, n0, 0);
    CP_COMMIT();

    float acc[4][4] = {};

    const int NCH = D / 64;   // 16
    for (int j = 0; j < NCH; j++) {
        uint32_t buf = (j & 1) ? QI_BUF : 0;
        if (j + 1 < NCH) {
            uint32_t nb = ((j + 1) & 1) ? QI_BUF : 0;
            int k0 = (j + 1) * 64;
            load_tile(nb + QI_AH, xh, m0, k0);
            load_tile(nb + QI_AL, xl, m0, k0);
            load_tile(nb + QI_BH, wh, n0, k0);
            load_tile(nb + QI_BL, wl, n0, k0);
            CP_COMMIT();
            CP_WAIT(1);
        } else {
            CP_WAIT(0);
        }
        __syncthreads();

        #pragma unroll
        for (int kk = 0; kk < 4; kk++) {
            uint32_t afh[4], afl[4];
            {
                int row = mbase + (lane & 15);
                int colb = kk * 32 + ((lane >> 4) << 4);
                uint32_t sw = (uint32_t)(colb ^ ((row & 7) << 4));
                LDSM_X4(afh[0], afh[1], afh[2], afh[3], sb + buf + QI_AH + row * 128 + sw);
                LDSM_X4(afl[0], afl[1], afl[2], afl[3], sb + buf + QI_AL + row * 128 + sw);
            }
            uint32_t bfh[4][2], bfl[4][2];
            #pragma unroll
            for (int bt = 0; bt < 2; bt++) {
                int nrow = nbase + bt * 16 + (lane & 7) + ((lane >> 4) << 3);
                int colb = kk * 32 + ((lane & 8) << 1);
                uint32_t sw = (uint32_t)(colb ^ ((nrow & 7) << 4));
                LDSM_X4(bfh[bt * 2][0], bfh[bt * 2][1], bfh[bt * 2 + 1][0], bfh[bt * 2 + 1][1],
                        sb + buf + QI_BH + nrow * 128 + sw);
                LDSM_X4(bfl[bt * 2][0], bfl[bt * 2][1], bfl[bt * 2 + 1][0], bfl[bt * 2 + 1][1],
                        sb + buf + QI_BL + nrow * 128 + sw);
            }
            #pragma unroll
            for (int nt = 0; nt < 4; nt++) {
                MMA16816H(acc[nt], afh, bfh[nt]);
                MMA16816H(acc[nt], afh, bfl[nt]);
                MMA16816H(acc[nt], afl, bfh[nt]);
            }
        }
        __syncthreads();
    }

    int r0 = m0 + mbase + (lane >> 2);
    #pragma unroll
    for (int nt = 0; nt < 4; nt++) {
        int cl = nbase + nt * 8 + 2 * (lane & 3);
        float b0 = biash[cl], b1 = biash[cl + 1];
        float2 v0 = make_float2(acc[nt][0] + b0, acc[nt][1] + b1);
        float2 v1 = make_float2(acc[nt][2] + b0, acc[nt][3] + b1);
        *(float2*)&C[(size_t)r0 * DKD + n0 + cl] = v0;
        *(float2*)&C[(size_t)(r0 + 8) * DKD + n0 + cl] = v1;
    }
}

// ---------------- fp8 tensor scan: e4m3 mma.sync, balanced 9-way key splits ------
// (R13-confirmed form: fresh per-tile block-wide max via shared atomics)
#define SO_A    0
#define SO_B0   32768
#define SO_B1   65536
#define SO_K2   98304
#define SO_SMAX 98816
#define SMEM_SCAN 99328

__global__ void __launch_bounds__(256, 2) scan_mma_kernel(
    const unsigned char* __restrict__ qf, const unsigned char* __restrict__ kf,
    const float* __restrict__ k2buf, int* __restrict__ cnt, int* __restrict__ cidx)
{
    extern __shared__ char smem[];
    uint32_t sb = smem_u32(smem);
    float*    k2h  = (float*)(smem + SO_K2);
    unsigned* smax = (unsigned*)(smem + SO_SMAX);

    int tid  = threadIdx.x;
    int lane = tid & 31, wid = tid >> 5;
    int tok0 = blockIdx.x * TOKS;
    // uneven split: splits 0-3 get 29 tiles, splits 4-8 get 28 (4*29+5*28=256)
    int s = blockIdx.y;
    int tile0  = s * 28 + min(s, 4);
    int ntiles = (s < 4) ? 29 : 28;
    int keybase = tile0 * KEYT;
    int mbase = (wid >> 1) * 32;
    int nhalf = (wid & 1) * 64;

    if (tid < TOKS) smax[tid] = fenc(-1e30f);

    {
        const char* abase = (const char*)(qf + (size_t)tok0 * DKD);
        const char* bbase = (const char*)(kf + (size_t)keybase * DKD);
        for (int i = tid; i < 2048; i += 256) {
            int row = i >> 4, c16 = i & 15;
            int colb = c16 * 16;
            uint32_t sw = (uint32_t)(colb ^ ((row & 7) << 4));
            CP_ASYNC16(sb + SO_A + row * 256 + sw, abase + row * 256 + colb);
            CP_ASYNC16(sb + SO_B0 + row * 256 + sw, bbase + row * 256 + colb);
        }
        CP_COMMIT();
    }

    float acc[2][8][4];

    for (int t = 0; t < ntiles; t++) {
        int key0 = keybase + t * KEYT;

        if (t + 1 < ntiles) {
            uint32_t nb = ((t + 1) & 1) ? SO_B1 : SO_B0;
            const char* bbase = (const char*)(kf + (size_t)(key0 + KEYT) * DKD);
            for (int i = tid; i < 2048; i += 256) {
                int row = i >> 4, c16 = i & 15;
                int colb = c16 * 16;
                uint32_t sw = (uint32_t)(colb ^ ((row & 7) << 4));
                CP_ASYNC16(sb + nb + row * 256 + sw, bbase + row * 256 + colb);
            }
            CP_COMMIT();
            CP_WAIT(1);
        } else {
            CP_WAIT(0);
        }
        __syncthreads();

        if (tid < KEYT) k2h[tid] = 0.5f * k2buf[key0 + tid];

        #pragma unroll
        for (int mt = 0; mt < 2; mt++)
            #pragma unroll
            for (int nt = 0; nt < 8; nt++)
                #pragma unroll
                for (int e = 0; e < 4; e++) acc[mt][nt][e] = 0.f;

        uint32_t bbuf = sb + ((t & 1) ? SO_B1 : SO_B0);
        #pragma unroll
        for (int kk = 0; kk < 8; kk++) {
            uint32_t a[2][4];
            #pragma unroll
            for (int mt = 0; mt < 2; mt++) {
                int row = mbase + mt * 16 + (lane & 15);
                int colb = kk * 32 + ((lane >> 4) << 4);
                uint32_t ad = sb + SO_A + row * 256 + (uint32_t)(colb ^ ((row & 7) << 4));
                LDSM_X4(a[mt][0], a[mt][1], a[mt][2], a[mt][3], ad);
            }
            uint32_t b[8][2];
            #pragma unroll
            for (int bt = 0; bt < 4; bt++) {
                int n = nhalf + bt * 16 + (lane & 7) + ((lane >> 4) << 3);
                int colb = kk * 32 + ((lane & 8) << 1);
                uint32_t bd = bbuf + n * 256 + (uint32_t)(colb ^ ((n & 7) << 4));
                LDSM_X4(b[bt * 2][0], b[bt * 2][1], b[bt * 2 + 1][0], b[bt * 2 + 1][1], bd);
            }
            #pragma unroll
            for (int mt = 0; mt < 2; mt++)
                #pragma unroll
                for (int nt = 0; nt < 8; nt++)
                    MMA16832F8(acc[mt][nt], a[mt], b[nt]);
        }
        __syncthreads();

        // epilogue: scores, running max, selection (fresh per-tile max)
        {
            float rm[2][2];
            #pragma unroll
            for (int mt = 0; mt < 2; mt++) { rm[mt][0] = -1e30f; rm[mt][1] = -1e30f; }
            #pragma unroll
            for (int mt = 0; mt < 2; mt++) {
                #pragma unroll
                for (int nt = 0; nt < 8; nt++) {
                    float kc0 = k2h[nhalf + nt * 8 + 2 * (lane & 3)];
                    float kc1 = k2h[nhalf + nt * 8 + 2 * (lane & 3) + 1];
                    acc[mt][nt][0] -= kc0; acc[mt][nt][1] -= kc1;
                    acc[mt][nt][2] -= kc0; acc[mt][nt][3] -= kc1;
                    rm[mt][0] = fmaxf(rm[mt][0], fmaxf(acc[mt][nt][0], acc[mt][nt][1]));
                    rm[mt][1] = fmaxf(rm[mt][1], fmaxf(acc[mt][nt][2], acc[mt][nt][3]));
                }
            }
            #pragma unroll
            for (int mt = 0; mt < 2; mt++) {
                #pragma unroll
                for (int e = 0; e < 2; e++) {
                    float v = rm[mt][e];
                    v = fmaxf(v, __shfl_xor_sync(0xffffffffu, v, 1));
                    v = fmaxf(v, __shfl_xor_sync(0xffffffffu, v, 2));
                    rm[mt][e] = v;
                }
            }
            if ((lane & 3) == 0) {
                #pragma unroll
                for (int mt = 0; mt < 2; mt++) {
                    int r = mbase + mt * 16 + (lane >> 2);
                    atomicMax(&smax[r], fenc(rm[mt][0]));
                    atomicMax(&smax[r + 8], fenc(rm[mt][1]));
                }
            }
            __syncthreads();
            #pragma unroll
            for (int mt = 0; mt < 2; mt++) {
                int r0 = mbase + mt * 16 + (lane >> 2);
                float th0 = fdec(smax[r0]) - DELTA_S;
                float th1 = fdec(smax[r0 + 8]) - DELTA_S;
                int tokA = tok0 + r0, tokB = tokA + 8;
                #pragma unroll
                for (int nt = 0; nt < 8; nt++) {
                    int keyc = key0 + nhalf + nt * 8 + 2 * (lane & 3);
                    if (acc[mt][nt][0] > th0) {
                        int pos = atomicAdd(&cnt[tokA], 1);
                        if (pos < CAP) cidx[(size_t)tokA * CAP + pos] = keyc;
                    }
                    if (acc[mt][nt][1] > th0) {
                        int pos = atomicAdd(&cnt[tokA], 1);
                        if (pos < CAP) cidx[(size_t)tokA * CAP + pos] = keyc + 1;
                    }
                    if (acc[mt][nt][2] > th1) {
                        int pos = atomicAdd(&cnt[tokB], 1);
                        if (pos < CAP) cidx[(size_t)tokB * CAP + pos] = keyc;
                    }
                    if (acc[mt][nt][3] > th1) {
                        int pos = atomicAdd(&cnt[tokB], 1);
                        if (pos < CAP) cidx[(size_t)tokB * CAP + pos] = keyc + 1;
                    }
                }
            }
        }
    }
}

// ---------------- exact rescore + 8-round recursion + gather (emits fp16) ----------
__global__ void recurse_kernel(const float* __restrict__ keys, const float* __restrict__ vals,
                               const float* __restrict__ qbuf, const float* __restrict__ q2buf,
                               const float* __restrict__ k2buf, const int* __restrict__ cnt,
                               const int* __restrict__ cidx,
                               __half* __restrict__ a16) {
    __shared__ float    qrow[DKD];
    __shared__ int      cidx_sh[CAP];
    __shared__ float    lg_all[CAP];
    __shared__ int      keep_idx[MAXKEEP];
    __shared__ float    keep_lg[MAXKEEP];
    __shared__ float    wmat[KN][MAXKEEP];
    __shared__ unsigned s_maxenc;
    __shared__ int      s_nkeep;

    int tok = blockIdx.x, tid = threadIdx.x;
    int lane = tid & 31, wid = tid >> 5;
    int n = min(cnt[tok], CAP);

    qrow[tid] = qbuf[(size_t)tok * DKD + tid];
    if (tid == 0) { s_maxenc = fenc(-1e30f); s_nkeep = 0; }
    for (int c = tid; c < n; c += 256) cidx_sh[c] = cidx[(size_t)tok * CAP + c];
    __syncthreads();

    float q2 = q2buf[tok];
    float4 q0 = *(const float4*)&qrow[lane * 4];
    float4 q1 = *(const float4*)&qrow[128 + lane * 4];
    for (int c0 = wid * 2; c0 < n; c0 += 16) {
        int kiA = cidx_sh[c0];
        bool hasB = (c0 + 1 < n);
        int kiB = hasB ? cidx_sh[c0 + 1] : kiA;
        const float4* kpA = (const float4*)(keys + (size_t)kiA * DKD);
        const float4* kpB = (const float4*)(keys + (size_t)kiB * DKD);
        float4 a0 = kpA[lane], a1 = kpA[lane + 32];
        float4 b0 = kpB[lane], b1 = kpB[lane + 32];
        float pA = q0.x * a0.x;
        pA = fmaf(q0.y, a0.y, pA); pA = fmaf(q0.z, a0.z, pA); pA = fmaf(q0.w, a0.w, pA);
        pA = fmaf(q1.x, a1.x, pA); pA = fmaf(q1.y, a1.y, pA);
        pA = fmaf(q1.z, a1.z, pA); pA = fmaf(q1.w, a1.w, pA);
        float pB = q0.x * b0.x;
        pB = fmaf(q0.y, b0.y, pB); pB = fmaf(q0.z, b0.z, pB); pB = fmaf(q0.w, b0.w, pB);
        pB = fmaf(q1.x, b1.x, pB); pB = fmaf(q1.y, b1.y, pB);
        pB = fmaf(q1.z, b1.z, pB); pB = fmaf(q1.w, b1.w, pB);
        #pragma unroll
        for (int o = 16; o; o >>= 1) {
            pA += __shfl_xor_sync(0xffffffffu, pA, o);
            pB += __shfl_xor_sync(0xffffffffu, pB, o);
        }
        if (lane == 0) {
            float lgA = -(q2 - 2.0f * pA + k2buf[kiA]) / 0.1f;
            lg_all[c0] = lgA;
            unsigned m = fenc(lgA);
            if (hasB) {
                float lgB = -(q2 - 2.0f * pB + k2buf[kiB]) / 0.1f;
                lg_all[c0 + 1] = lgB;
                unsigned mB = fenc(lgB);
                if (mB > m) m = mB;
            }
            atomicMax(&s_maxenc, m);
        }
    }
    __syncthreads();
    float cut = fdec(s_maxenc) - CUT_LG;
    for (int c = tid; c < n; c += 256) {
        if (lg_all[c] >= cut) {
            int pos = atomicAdd(&s_nkeep, 1);
            if (pos < MAXKEEP) {
                keep_idx[pos] = cidx_sh[c];
                keep_lg[pos]  = lg_all[c];
            }
        }
    }
    __syncthreads();
    int nk = min(s_nkeep, MAXKEEP);
    {
        int my = 0, rank = -1; float mylg = 0.f;
        if (tid < nk) {
            my = keep_idx[tid]; mylg = keep_lg[tid];
            rank = 0;
            for (int c = 0; c < nk; c++) rank += (keep_idx[c] < my);
        }
        __syncthreads();
        if (tid < nk) { keep_idx[rank] = my; keep_lg[rank] = mylg; }
        __syncthreads();
    }
    if (wid == 0) {
        for (int k = 0; k < KN; k++) {
            float lm = -1e30f;
            for (int c = lane; c < nk; c += 32) lm = fmaxf(lm, keep_lg[c]);
            #pragma unroll
            for (int o = 16; o; o >>= 1) lm = fmaxf(lm, __shfl_xor_sync(0xffffffffu, lm, o));
            float zs = 0.f;
            for (int c = lane; c < nk; c += 32) {
                float p = expf(keep_lg[c] - lm);
                wmat[k][c] = p;
                zs += p;
            }
            #pragma unroll
            for (int o = 16; o; o >>= 1) zs += __shfl_xor_sync(0xffffffffu, zs, o);
            float inv = 1.0f / zs;
            for (int c = lane; c < nk; c += 32) {
                float w = wmat[k][c] * inv;
                wmat[k][c] = w;
                keep_lg[c] += log1pf(-w + 1e-6f);
            }
            __syncwarp();
        }
    }
    __syncthreads();
    float a[KN] = {};
    for (int c = 0; c < nk; c++) {
        float v = vals[(size_t)keep_idx[c] * DM + tid];
        #pragma unroll
        for (int k = 0; k < KN; k++) a[k] = fmaf(wmat[k][c], v, a[k]);
    }
    #pragma unroll
    for (int k = 0; k < KN; k++)
        a16[(size_t)tok * FF + k * DM + tid] = __float2half_rn(a[k]);
}

// ---------------- W_out GEMM: fp16 tensor cores, double buffer, 2 CTA/SM ----------
#define WO_A    0
#define WO_B    16384
#define WO_BUF  32768
#define WO_BIAS 65536
#define SMEM_WOUT 66048

__global__ void __launch_bounds__(256, 2) wout_mma_kernel(
    const __half* __restrict__ a16, const __half* __restrict__ w16,
    const float* __restrict__ bias, float* __restrict__ C)
{
    extern __shared__ char smem[];
    uint32_t sb = smem_u32(smem);
    float* biash = (float*)(smem + WO_BIAS);

    int tid  = threadIdx.x;
    int lane = tid & 31, wid = tid >> 5;
    int m0 = blockIdx.x * 128, n0 = blockIdx.y * 128;
    int mbase = (wid >> 1) * 32;
    int nhalf = (wid & 1) * 64;

    if (tid < 128) biash[tid] = bias[n0 + tid];

    auto load_tile = [&](uint32_t dst, const __half* src, int row0, int k0) {
        const char* base = (const char*)(src + (size_t)row0 * FF + k0);
        for (int i = tid; i < 1024; i += 256) {
            int row = i >> 3, c16 = i & 7;
            int colb = c16 * 16;
            uint32_t sw = (uint32_t)(colb ^ ((row & 7) << 4));
            CP_ASYNC16(sb + dst + row * 128 + sw, base + (size_t)row * (FF * 2) + colb);
        }
    };

    load_tile(WO_A, a16, m0, 0);
    load_tile(WO_B, w16, n0, 0);
    CP_COMMIT();

    float acc[2][8][4] = {};

    const int NCH = FF / 64;   // 32
    for (int j = 0; j < NCH; j++) {
        uint32_t buf = (j & 1) ? WO_BUF : 0;
        if (j + 1 < NCH) {
            uint32_t nb = ((j + 1) & 1) ? WO_BUF : 0;
            int k0 = (j + 1) * 64;
            load_tile(nb + WO_A, a16, m0, k0);
            load_tile(nb + WO_B, w16, n0, k0);
            CP_COMMIT();
            CP_WAIT(1);
        } else {
            CP_WAIT(0);
        }
        __syncthreads();

        #pragma unroll
        for (int kk = 0; kk < 4; kk++) {
            uint32_t af[2][4];
            #pragma unroll
            for (int mt = 0; mt < 2; mt++) {
                int row = mbase + mt * 16 + (lane & 15);
                int colb = kk * 32 + ((lane >> 4) << 4);
                uint32_t sw = (uint32_t)(colb ^ ((row & 7) << 4));
                LDSM_X4(af[mt][0], af[mt][1], af[mt][2], af[mt][3],
                        sb + buf + WO_A + row * 128 + sw);
            }
            uint32_t bf[8][2];
            #pragma unroll
            for (int bt = 0; bt < 4; bt++) {
                int nrow = nhalf + bt * 16 + (lane & 7) + ((lane >> 4) << 3);
                int colb = kk * 32 + ((lane & 8) << 1);
                uint32_t sw = (uint32_t)(colb ^ ((nrow & 7) << 4));
                LDSM_X4(bf[bt * 2][0], bf[bt * 2][1], bf[bt * 2 + 1][0], bf[bt * 2 + 1][1],
                        sb + buf + WO_B + nrow * 128 + sw);
            }
            #pragma unroll
            for (int mt = 0; mt < 2; mt++)
                #pragma unroll
                for (int nt = 0; nt < 8; nt++)
                    MMA16816H(acc[mt][nt], af[mt], bf[nt]);
        }
        __syncthreads();
    }

    #pragma unroll
    for (int mt = 0; mt < 2; mt++) {
        int r0 = m0 + mbase + mt * 16 + (lane >> 2);
        #pragma unroll
        for (int nt = 0; nt < 8; nt++) {
            int cl = nhalf + nt * 8 + 2 * (lane & 3);
            float b0 = biash[cl], b1 = biash[cl + 1];
            float2 v0 = make_float2(acc[mt][nt][0] + b0, acc[mt][nt][1] + b1);
            float2 v1 = make_float2(acc[mt][nt][2] + b0, acc[mt][nt][3] + b1);
            *(float2*)&C[(size_t)r0 * D + n0 + cl] = v0;
            *(float2*)&C[(size_t)(r0 + 8) * D + n0 + cl] = v1;
        }
    }
}

// ---------------- RMSNorm (in place on d_out) ----------------
__global__ void rmsnorm_kernel(float* __restrict__ out, const float* __restrict__ rms_w) {
    __shared__ float wsum[8];
    __shared__ float s_tot;
    int tok = blockIdx.x, tid = threadIdx.x;
    float* row = out + (size_t)tok * D;
    float v[4];
    float ss = 0.f;
    #pragma unroll
    for (int e = 0; e < 4; e++) { v[e] = row[tid + e * 256]; ss = fmaf(v[e], v[e], ss); }
    #pragma unroll
    for (int o = 16; o; o >>= 1) ss += __shfl_xor_sync(0xffffffffu, ss, o);
    if ((tid & 31) == 0) wsum[tid >> 5] = ss;
    __syncthreads();
    if (tid == 0) {
        float t = 0.f;
        #pragma unroll
        for (int w = 0; w < 8; w++) t += wsum[w];
        s_tot = t;
    }
    __syncthreads();
    float var = s_tot / (float)D;
    float rs = 1.0f / sqrtf(var + 1e-6f);
    #pragma unroll
    for (int e = 0; e < 4; e++) {
        int d = tid + e * 256;
        row[d] = rms_w[d] * (v[e] * rs);
    }
}

// ---------------- host launch ----------------
extern "C" void kernel_launch(void* const* d_in, const int* in_sizes, int n_in,
                              void* d_out, int out_size) {
    const float* x     = (const float*)d_in[0];
    const float* keys  = (const float*)d_in[1];
    const float* vals  = (const float*)d_in[2];
    const float* W_in  = (const float*)d_in[3];
    const float* b_in  = (const float*)d_in[4];
    const float* W_out = (const float*)d_in[5];
    const float* b_out = (const float*)d_in[6];
    const float* rms_w = (const float*)d_in[7];
    float* out = (float*)d_out;
    (void)in_sizes; (void)n_in; (void)out_size;

    float *qp, *q2p, *k2p;
    int *cntp, *cidxp;
    unsigned char *kfp, *qfp;
    __half *a16p, *w16p, *xhp, *xlp, *wihp, *wilp;
    cudaGetSymbolAddress((void**)&qp,    g_q);
    cudaGetSymbolAddress((void**)&q2p,   g_q2);
    cudaGetSymbolAddress((void**)&k2p,   g_k2);
    cudaGetSymbolAddress((void**)&cntp,  g_cnt);
    cudaGetSymbolAddress((void**)&cidxp, g_cidx);
    cudaGetSymbolAddress((void**)&kfp,   g_keys_f8);
    cudaGetSymbolAddress((void**)&qfp,   g_q_f8);
    cudaGetSymbolAddress((void**)&a16p,  g_a16);
    cudaGetSymbolAddress((void**)&w16p,  g_w16);
    cudaGetSymbolAddress((void**)&xhp,   g_xh);
    cudaGetSymbolAddress((void**)&xlp,   g_xl);
    cudaGetSymbolAddress((void**)&wihp,  g_wih);
    cudaGetSymbolAddress((void**)&wilp,  g_wil);

    static int smem_set = 0;
    if (!smem_set) {
        cudaFuncSetAttribute(scan_mma_kernel, cudaFuncAttributeMaxDynamicSharedMemorySize, SMEM_SCAN);
        cudaFuncSetAttribute(wout_mma_kernel, cudaFuncAttributeMaxDynamicSharedMemorySize, SMEM_WOUT);
        cudaFuncSetAttribute(qin_mma_kernel,  cudaFuncAttributeMaxDynamicSharedMemorySize, SMEM_QIN);
        smem_set = 1;
    }

    // 1. merged prep: keys k2+fp8 | W_out fp16 | x, W_in split-fp16 (one launch)
    prep_all_kernel<<<PREP_BLOCKS, 256>>>(keys, kfp, k2p, W_out, w16p,
                                          x, xhp, xlp, W_in, wihp, wilp);
    // 2. q = x @ W_in^T + b_in (split-fp16 tensor cores, fp32-exact)
    qin_mma_kernel<<<dim3(R / 64, DKD / 64), 256, SMEM_QIN>>>(xhp, xlp, wihp, wilp, b_in, qp);
    // 3. q: q2 + fp8 convert + cnt reset (fused)
    prep_q_kernel<<<R / 8, 256>>>(qp, qfp, q2p, cntp);
    // 4. fp8 tensor-core qk scan + candidate selection (288 balanced CTAs, R13 form)
    scan_mma_kernel<<<dim3(R / TOKS, KSPLIT), 256, SMEM_SCAN>>>(qfp, kfp, k2p, cntp, cidxp);
    // 5. exact rescore + 8-round recursion + gather -> fp16 nearest
    recurse_kernel<<<R, 256>>>(keys, vals, qp, q2p, k2p, cntp, cidxp, a16p);
    // 6. out = nearest @ W_out^T + b_out (fp16 tensor cores)
    wout_mma_kernel<<<dim3(R / 128, D / 128), 256, SMEM_WOUT>>>(a16p, w16p, b_out, out);
    // 7. RMSNorm * rms_w, in place
    rmsnorm_kernel<<<R, 256>>>(out, rms_w);
}